// round 16
// baseline (speedup 1.0000x reference)
#include <cuda_runtime.h>
#include <stdint.h>

#define BB 256
#define TT 32768
#define TT4 (TT / 4)
#define KK 3
#define ALPHA 0.95f
#define THETA 0.05f
#define LCH 256          // chunk length
#define NCH (TT / LCH)   // 128 chunks
#define WMAX 512         // max warmup steps
#define G 8              // float4 groups (4 steps each) in flight per plane

typedef unsigned long long ull;

// scratch: u in blocked transpose [k][t/4][b][4] + pad covering the register
// pipeline's worst-case overrun (last chunk reads ~71 groups past TT4)
__device__ float g_uB[KK * TT4 * BB * 4 + 131072];

#define PACK2(dst, lo, hi) \
    asm("mov.b64 %0, {%1, %2};" : "=l"(dst) : "f"(lo), "f"(hi))
#define UNPACK2(lo, hi, src) \
    asm("mov.b64 {%0, %1}, %2;" : "=f"(lo), "=f"(hi) : "l"(src))
#define FMA2(acc, a, b) \
    asm("fma.rn.f32x2 %0, %1, %2, %0;" : "+l"(acc) : "l"(a), "l"(b))

// ---------------------------------------------------------------------------
// Kernel 1: causal convs (R14 exact). Tile = 32 b x 64 t, FFMA2 pairs.
// u bit-identical to all validated rounds.
// ---------------------------------------------------------------------------
__global__ void __launch_bounds__(256) conv_kernel(const float* __restrict__ x,
                                                   const float* __restrict__ w8,
                                                   const float* __restrict__ w16,
                                                   const float* __restrict__ w32,
                                                   float* __restrict__ u_out) {
    __shared__ __align__(8) float2 wf2[64]; // duplicated flipped weights
    __shared__ __align__(16) float buf[KK * 32 * 69];
    float (*xs)[100]    = reinterpret_cast<float (*)[100]>(buf);     // 32 x 100
    float (*us)[32][69] = reinterpret_cast<float (*)[32][69]>(buf);  // 3 x 32 x 69

    const int tid    = threadIdx.x;
    const int w      = tid >> 5;
    const int l      = tid & 31;
    const int tile_t = blockIdx.x * 64;
    const int b0     = blockIdx.y * 32;

    if (tid < 32)       { float v = w32[31 - tid];  wf2[tid] = make_float2(v, v); }
    else if (tid < 48)  { float v = w16[47 - tid];  wf2[tid] = make_float2(v, v); }
    else if (tid < 56)  { float v = w8[55 - tid];   wf2[tid] = make_float2(v, v); }

    // phase A (vectorized): xs[r][4*c4..] = x[b0+r][tile_t-32+4*c4..]
    {
        const int r  = 4 * w + (l >> 3);
        const int c4 = l & 7;
        const float4* xrow = (const float4*)(x + (size_t)(b0 + r) * TT + tile_t - 32);
        float4* xsrow = (float4*)&xs[r][0];
        if (tile_t == 0) {
            xsrow[c4] = make_float4(0.f, 0.f, 0.f, 0.f);   // left halo = zeros
        } else {
            xsrow[c4] = xrow[c4];
        }
        xsrow[c4 + 8]  = xrow[c4 + 8];
        xsrow[c4 + 16] = xrow[c4 + 16];
    }
    __syncthreads();

    // phase B: window win[i] = x[tile_t + tq + i - 32], packed into pairs
    const int bl = l;
    const int tq = w * 8;
    ull E[20], O[19];
    {
        const float4* wrow = (const float4*)&xs[bl][tq];
        float prev_w = 0.0f;
#pragma unroll
        for (int i4 = 0; i4 < 10; i4++) {
            float4 v = wrow[i4];
            PACK2(E[2 * i4],     v.x, v.y);
            PACK2(E[2 * i4 + 1], v.z, v.w);
            if (i4 > 0) PACK2(O[2 * i4 - 1], prev_w, v.x);
            if (i4 < 10) PACK2(O[2 * i4], v.y, v.z);
            prev_w = v.w;
        }
    }
    __syncthreads();   // xs dead; union reused as us

    ull A32[4] = {0,0,0,0}, A16[4] = {0,0,0,0}, A8[4] = {0,0,0,0};
    const ull* wfp = (const ull*)wf2;

#pragma unroll
    for (int d = 0; d < 32; d++) {
        ull wv = wfp[d];
        const int base = 32 - d;
#pragma unroll
        for (int p = 0; p < 4; p++) {
            if ((base & 1) == 0) { FMA2(A32[p], wv, E[(base >> 1) + p]); }
            else                 { FMA2(A32[p], wv, O[((base - 1) >> 1) + p]); }
        }
    }
#pragma unroll
    for (int d = 0; d < 16; d++) {
        ull wv = wfp[32 + d];
        const int base = 32 - d;
#pragma unroll
        for (int p = 0; p < 4; p++) {
            if ((base & 1) == 0) { FMA2(A16[p], wv, E[(base >> 1) + p]); }
            else                 { FMA2(A16[p], wv, O[((base - 1) >> 1) + p]); }
        }
    }
#pragma unroll
    for (int d = 0; d < 8; d++) {
        ull wv = wfp[48 + d];
        const int base = 32 - d;
#pragma unroll
        for (int p = 0; p < 4; p++) {
            if ((base & 1) == 0) { FMA2(A8[p], wv, E[(base >> 1) + p]); }
            else                 { FMA2(A8[p], wv, O[((base - 1) >> 1) + p]); }
        }
    }

#pragma unroll
    for (int p = 0; p < 4; p++) {
        float lo, hi;
        UNPACK2(lo, hi, A8[p]);
        us[0][bl][tq + 2 * p] = lo;  us[0][bl][tq + 2 * p + 1] = hi;
        UNPACK2(lo, hi, A16[p]);
        us[1][bl][tq + 2 * p] = lo;  us[1][bl][tq + 2 * p + 1] = hi;
        UNPACK2(lo, hi, A32[p]);
        us[2][bl][tq + 2 * p] = lo;  us[2][bl][tq + 2 * p + 1] = hi;
    }
    __syncthreads();

    // phase D: u_out [b][k][t] (warp writes 128B rows)
#pragma unroll
    for (int bbq = 0; bbq < 4; bbq++) {
        int bb = w * 4 + bbq;
        float* orow = u_out + (size_t)(b0 + bb) * 3 * TT + tile_t;
#pragma unroll
        for (int k = 0; k < 3; k++)
#pragma unroll
            for (int h = 0; h < 2; h++)
                orow[(size_t)k * TT + 32 * h + l] = us[k][bb][32 * h + l];
    }
    // phase E: g_uB [k][tg][b][4] (lane = b, warp writes 512B chunks)
#pragma unroll
    for (int r = 0; r < 6; r++) {
        int row = w + r * 8;          // 0..47 = k*16 + tgl
        int k   = row >> 4;
        int tgl = row & 15;
        float4 v;
        v.x = us[k][l][tgl * 4 + 0];
        v.y = us[k][l][tgl * 4 + 1];
        v.z = us[k][l][tgl * 4 + 2];
        v.w = us[k][l][tgl * 4 + 3];
        *(float4*)&g_uB[(((size_t)k * TT4 + (tile_t >> 2) + tgl) * BB + b0 + l) * 4] = v;
    }
}

// ---------------------------------------------------------------------------
// Kernel 2: chunked WTA-LIF scan. Predicate-free WTA: FSET float masks
// (set.ge/gt.f32.f32 -> 1.0f/0.0f, fixed-lat 4, fma pipe) and v updates via
// fma(-theta, mask, v) -- bit-identical to the validated select form.
// ---------------------------------------------------------------------------
__device__ __forceinline__ float fset_ge(float a, float b) {
    float d; asm("set.ge.f32.f32 %0, %1, %2;" : "=f"(d) : "f"(a), "f"(b)); return d;
}
__device__ __forceinline__ float fset_gt(float a, float b) {
    float d; asm("set.gt.f32.f32 %0, %1, %2;" : "=f"(d) : "f"(a), "f"(b)); return d;
}

__device__ __forceinline__ void lif_step_f(float& v0, float& v1, float& v2,
                                           float u0, float u1, float u2,
                                           float& s0f, float& s1f, float& s2f) {
    v0 = fmaf(ALPHA, v0, u0);
    v1 = fmaf(ALPHA, v1, u1);
    v2 = fmaf(ALPHA, v2, u2);
    float gt10 = fset_gt(v1, v0);          // v1 >  v0
    float gt20 = fset_gt(v2, v0);          // v2 >  v0
    float gt21 = fset_gt(v2, v1);          // v2 >  v1
    float th0  = fset_ge(v0, THETA);
    float th1  = fset_ge(v1, THETA);
    float th2  = fset_ge(v2, THETA);
    // winner-take-all, argmax first-index tie-break, spike iff winner >= theta
    s0f = (1.0f - gt10) * (1.0f - gt20) * th0;
    s1f = gt10 * (1.0f - gt21) * th1;
    s2f = gt20 * gt21 * th2;
    v0 = fmaf(-THETA, s0f, v0);
    v1 = fmaf(-THETA, s1f, v1);
    v2 = fmaf(-THETA, s2f, v2);
}

__global__ void __launch_bounds__(128) scan_kernel(float* __restrict__ out_s) {
    __shared__ uint32_t sb[KK][LCH / 32][128];   // per-thread masks [k][window][b], 12 KB

    const int tid    = threadIdx.x;
    const int b0s    = (blockIdx.x & 1) * 128;
    const int c      = blockIdx.x >> 1;
    const int b      = b0s + tid;
    const int out_t0 = c * LCH;
    const int t0     = (out_t0 > WMAX) ? (out_t0 - WMAX) : 0;
    const int nw     = out_t0 - t0;      // warmup steps (0, 256, or 512)
    const int gb0    = t0 >> 2;          // starting group index

    const float4* p0 = (const float4*)g_uB + ((size_t)0 * TT4 + gb0) * BB + b;
    const float4* p1 = (const float4*)g_uB + ((size_t)1 * TT4 + gb0) * BB + b;
    const float4* p2 = (const float4*)g_uB + ((size_t)2 * TT4 + gb0) * BB + b;

    float4 q0[G], q1[G], q2[G];
#pragma unroll
    for (int i = 0; i < G; i++) {
        q0[i] = __ldg(p0 + (size_t)i * BB);
        q1[i] = __ldg(p1 + (size_t)i * BB);
        q2[i] = __ldg(p2 + (size_t)i * BB);
    }

    float v0 = 0.f, v1 = 0.f, v2 = 0.f;
    float s0f, s1f, s2f;

    // ---- warmup: windows of 8 groups (32 steps) ----
    const int nww = nw >> 5;             // 0, 8, or 16 windows
    for (int ww = 0; ww < nww; ww++) {
#pragma unroll
        for (int gg = 0; gg < 8; gg++) {
            float4 a = q0[gg], bq = q1[gg], cq = q2[gg];
            q0[gg] = __ldg(p0 + (size_t)(gg + G) * BB);
            q1[gg] = __ldg(p1 + (size_t)(gg + G) * BB);
            q2[gg] = __ldg(p2 + (size_t)(gg + G) * BB);
            lif_step_f(v0, v1, v2, a.x, bq.x, cq.x, s0f, s1f, s2f);
            lif_step_f(v0, v1, v2, a.y, bq.y, cq.y, s0f, s1f, s2f);
            lif_step_f(v0, v1, v2, a.z, bq.z, cq.z, s0f, s1f, s2f);
            lif_step_f(v0, v1, v2, a.w, bq.w, cq.w, s0f, s1f, s2f);
        }
        p0 += (size_t)8 * BB; p1 += (size_t)8 * BB; p2 += (size_t)8 * BB;
    }

    // ---- main: 8 windows of 32 steps; thread-local bit packing ----
    for (int w32 = 0; w32 < LCH / 32; w32++) {
        uint32_t m0 = 0, m1 = 0, m2 = 0;
#pragma unroll
        for (int gg = 0; gg < 8; gg++) {
            float4 a = q0[gg], bq = q1[gg], cq = q2[gg];
            q0[gg] = __ldg(p0 + (size_t)(gg + G) * BB);
            q1[gg] = __ldg(p1 + (size_t)(gg + G) * BB);
            q2[gg] = __ldg(p2 + (size_t)(gg + G) * BB);
#pragma unroll
            for (int j = 0; j < 4; j++) {
                float u0 = (j == 0) ? a.x  : (j == 1) ? a.y  : (j == 2) ? a.z  : a.w;
                float u1 = (j == 0) ? bq.x : (j == 1) ? bq.y : (j == 2) ? bq.z : bq.w;
                float u2 = (j == 0) ? cq.x : (j == 1) ? cq.y : (j == 2) ? cq.z : cq.w;
                lif_step_f(v0, v1, v2, u0, u1, u2, s0f, s1f, s2f);
                const uint32_t bit = 1u << (gg * 4 + j);
                if (s0f != 0.0f) m0 |= bit;     // off the v-dependency chain
                if (s1f != 0.0f) m1 |= bit;
                if (s2f != 0.0f) m2 |= bit;
            }
        }
        p0 += (size_t)8 * BB; p1 += (size_t)8 * BB; p2 += (size_t)8 * BB;
        sb[0][w32][tid] = m0;
        sb[1][w32][tid] = m1;
        sb[2][w32][tid] = m2;
    }
    __syncthreads();

    // ---- fused expansion: 128 b x 3 k x 256 t floats for this block ----
    for (int f = tid; f < 128 * 3 * (LCH / 4); f += 128) {
        int t4 = f & (LCH / 4 - 1);
        int r  = f >> 6;
        int bq = r / 3;
        int k  = r - bq * 3;
        uint32_t wv = sb[k][t4 >> 3][bq];
        int sh = (t4 & 7) * 4;
        float4 o;
        o.x = (float)((wv >> (sh + 0)) & 1u);
        o.y = (float)((wv >> (sh + 1)) & 1u);
        o.z = (float)((wv >> (sh + 2)) & 1u);
        o.w = (float)((wv >> (sh + 3)) & 1u);
        *(float4*)(out_s + ((size_t)(b0s + bq) * 3 + k) * TT + out_t0 + t4 * 4) = o;
    }
}

// ---------------------------------------------------------------------------
extern "C" void kernel_launch(void* const* d_in, const int* in_sizes, int n_in,
                              void* d_out, int out_size) {
    const float* x   = (const float*)d_in[0];
    // d_in[1] = y, unused by the reference outputs
    const float* w8  = (const float*)d_in[2];
    const float* w16 = (const float*)d_in[3];
    const float* w32 = (const float*)d_in[4];
    float* out = (float*)d_out;

    conv_kernel<<<dim3(TT / 64, BB / 32), 256>>>(x, w8, w16, w32, out);
    scan_kernel<<<NCH * 2, 128>>>(out + (size_t)BB * KK * TT);
}